// round 4
// baseline (speedup 1.0000x reference)
#include <cuda_runtime.h>
#include <cstdint>

// out[dst[e]*64 + j] += src_emb[src[e]*64 + j] * att[e]
// D = 64 floats = 16 float4-lanes per edge.
// Block of 256 threads processes 128 edges (2048 lane-tasks, 8 per thread).
// Tail edges map to idx 0 with att 0 -> REDG adds exact 0.0f (branch-free).

static constexpr int D = 64;
static constexpr int EPB = 128;         // edges per block
static constexpr int TASKS = 8;         // lane-tasks per thread (EPB*16/256)

__global__ __launch_bounds__(256)
void scatter_mul_sum_kernel(const float* __restrict__ src_emb,
                            const float* __restrict__ e_att,
                            const int* __restrict__ src_idx,
                            const int* __restrict__ dst_idx,
                            float* __restrict__ out,
                            int num_edges)
{
    __shared__ int   s_src[EPB];
    __shared__ int   s_dst[EPB];
    __shared__ float s_att[EPB];

    const int t = threadIdx.x;
    const int base = blockIdx.x * EPB;

    // Stage edge metadata once per block. Invalid edges -> idx 0, att 0.
    if (t < EPB) {
        const int e = base + t;
        const bool valid = e < num_edges;
        s_src[t] = valid ? src_idx[e] : 0;
        s_dst[t] = valid ? dst_idx[e] : 0;
        s_att[t] = valid ? e_att[e]   : 0.0f;
    }
    __syncthreads();

    // Decode 8 tasks: 32-bit element offsets (max 50000*64 = 3.2M, fits).
    unsigned goff[TASKS], doff[TASKS];
    float att[TASKS];
#pragma unroll
    for (int k = 0; k < TASKS; k++) {
        const int task = t + k * 256;
        const int le   = task >> 4;       // edge slot in block
        const int lane = task & 15;       // float4 slot within row
        goff[k] = (unsigned)s_src[le] * D + lane * 4;
        doff[k] = (unsigned)s_dst[le] * D + lane * 4;
        att[k]  = s_att[le];
    }

    // Batched gathers: 8 independent LDG.128 in flight per thread.
    float4 v[TASKS];
#pragma unroll
    for (int k = 0; k < TASKS; k++) {
        v[k] = __ldcg(reinterpret_cast<const float4*>(src_emb + goff[k]));
    }

#pragma unroll
    for (int k = 0; k < TASKS; k++) {
        const float a = att[k];
        const float x = v[k].x * a;
        const float y = v[k].y * a;
        const float z = v[k].z * a;
        const float w = v[k].w * a;
        // Fire-and-forget vector reduction; tail tasks add exact zeros.
        asm volatile("red.global.add.v4.f32 [%0], {%1, %2, %3, %4};"
                     :: "l"(out + doff[k]), "f"(x), "f"(y), "f"(z), "f"(w)
                     : "memory");
    }
}

extern "C" void kernel_launch(void* const* d_in, const int* in_sizes, int n_in,
                              void* d_out, int out_size)
{
    const float* src_emb = (const float*)d_in[0];   // [N_SRC, 64]
    const float* e_att   = (const float*)d_in[1];   // [E, 1]
    const int*   src_idx = (const int*)d_in[2];     // [E] int32
    const int*   dst_idx = (const int*)d_in[3];     // [E] int32
    float* out = (float*)d_out;                     // [N_DST, 64]

    const int E = in_sizes[2];

    cudaMemsetAsync(d_out, 0, (size_t)out_size * sizeof(float), 0);

    const int grid = (E + EPB - 1) / EPB;
    scatter_mul_sum_kernel<<<grid, 256>>>(src_emb, e_att, src_idx, dst_idx, out, E);
}